// round 8
// baseline (speedup 1.0000x reference)
#include <cuda_runtime.h>
#include <cstdint>

#define S_LEN 2048
#define BATCH 256
#define HID   8
#define NBLK  80
#define OUTSZ 128
#define NROWS (S_LEN*BATCH)   // 524288
#define CHUNK_T 128
#define NCHUNK  (S_LEN/CHUNK_T)   // 16
#define K2_CTAS 8
#define PF 8

// Scratch (__device__ globals; no runtime allocation)
// g_xg layout: [row][unit*4 + gate_type], row = t*BATCH + b
__device__ float g_xg[(size_t)NROWS * 32];   // 64 MB
__device__ float g_ys[(size_t)NROWS * HID];  // 16 MB
__device__ int   g_k1done[NCHUNK];
__device__ int   g_k2done[NCHUNK];

__device__ __forceinline__ float tanha(float x) {
    float r; asm("tanh.approx.f32 %0, %1;" : "=f"(r) : "f"(x)); return r;
}
__device__ __forceinline__ float leaky(float v) { return fmaxf(v, 0.01f * v); }
// L2-only load (skip L1: cross-CTA produced data within one launch)
__device__ __forceinline__ float4 ldcg4(const float4* p) {
    float4 v;
    asm volatile("ld.global.cg.v4.f32 {%0,%1,%2,%3},[%4];"
                 : "=f"(v.x), "=f"(v.y), "=f"(v.z), "=f"(v.w) : "l"(p));
    return v;
}

union SmemU {
    struct { float4 sx[256 * 8]; float swp[32 * 33]; } k1;   // ~37 KB
    struct { float sh[8][2][32]; } k2;
    struct { float4 w1[NBLK], w2[NBLK], b2[NBLK]; float b1[NBLK]; } k3;
};

__global__ void k0_reset() {
    if (threadIdx.x < NCHUNK) {
        g_k1done[threadIdx.x] = 0;
        g_k2done[threadIdx.x] = 0;
    }
}

__global__ void __launch_bounds__(256) k_fused(
    const float* __restrict__ x,     const float* __restrict__ h0,
    const float* __restrict__ c0,    const float* __restrict__ w_ih,
    const float* __restrict__ w_hh,  const float* __restrict__ b_ih,
    const float* __restrict__ b_hh,
    const float* __restrict__ w_in,  const float* __restrict__ b_in,
    const float* __restrict__ rb_w1, const float* __restrict__ rb_b1,
    const float* __restrict__ rb_w2, const float* __restrict__ rb_b2,
    const float* __restrict__ w_bn,  const float* __restrict__ b_bn,
    const float* __restrict__ w_out, const float* __restrict__ b_out,
    float* __restrict__ out)
{
    __shared__ SmemU sm;
    const int bid  = blockIdx.x;
    const int tid  = threadIdx.x;
    const int lane = tid & 31;
    const int wid  = tid >> 5;

    // =====================================================================
    // K1 role: bids [K2_CTAS, K2_CTAS+S_LEN). One CTA = one timestep t.
    // xg[row][u*4+ty] = s(ty) * ( x[row].w_ih[ty*8+u] + b_ih + b_hh )
    // =====================================================================
    if (bid >= K2_CTAS && bid < K2_CTAS + S_LEN) {
        const int t = bid - K2_CTAS;

#pragma unroll
        for (int k = 0; k < 4; k++) {
            const int idx = tid + k * 256;          // 1024 floats
            const int g = idx >> 5, j = idx & 31;
            const float s = ((g >> 3) == 2) ? 1.f : 0.5f;
            sm.k1.swp[g * 33 + j] = w_ih[idx] * s;
        }

        const size_t rowbase = (size_t)t * 256;
        const float4* xg4 = (const float4*)x + rowbase * 8;
#pragma unroll
        for (int i = 0; i < 8; i++) sm.k1.sx[tid + i * 256] = xg4[tid + i * 256];

        __syncthreads();

        float w[32];
#pragma unroll
        for (int j = 0; j < 32; j++) w[j] = sm.k1.swp[lane * 33 + j];
        const float s2 = ((lane >> 3) == 2) ? 1.f : 0.5f;
        const float bias = (b_ih[lane] + b_hh[lane]) * s2;

        const int ocol = (lane & 7) * 4 + (lane >> 3);   // unit-major column
        float* op = g_xg + (rowbase + wid * 32) * 32 + ocol;
        const float4* xr0 = &sm.k1.sx[wid * 32 * 8];

#pragma unroll 4
        for (int r = 0; r < 32; r++) {
            const float4* xr = xr0 + r * 8;
            float a0 = bias, a1 = 0.f, a2 = 0.f, a3 = 0.f;
#pragma unroll
            for (int j4 = 0; j4 < 8; j4++) {
                const float4 v = xr[j4];
                a0 = fmaf(w[j4 * 4 + 0], v.x, a0);
                a1 = fmaf(w[j4 * 4 + 1], v.y, a1);
                a2 = fmaf(w[j4 * 4 + 2], v.z, a2);
                a3 = fmaf(w[j4 * 4 + 3], v.w, a3);
            }
            op[(size_t)r * 32] = (a0 + a1) + (a2 + a3);
        }

        __syncthreads();
        if (tid == 0) { __threadfence(); atomicAdd(&g_k1done[t >> 7], 1); }
        return;
    }

    // =====================================================================
    // K2 role: bids [0, K2_CTAS). 8 warps/CTA, 4 chains/warp = 256 chains.
    // lane = bsub*8+unit; lane computes all 4 gates of its unit.
    // Gated per 128-step chunk on k1done; signals k2done.
    // =====================================================================
    if (bid < K2_CTAS) {
        const int blk  = bid * 8 + wid;        // 0..63
        const int unit = lane & 7;
        const int bsub = lane >> 3;

        float w[4][8];
#pragma unroll
        for (int ty = 0; ty < 4; ty++) {
            const float s = (ty == 2) ? 1.f : 0.5f;
#pragma unroll
            for (int j = 0; j < 8; j++)
                w[ty][j] = w_hh[(ty * 8 + unit) * 8 + j] * s;
        }

        float h = h0[blk * 32 + lane];
        float c = c0[blk * 32 + lane];

        const float4* xp = (const float4*)g_xg + (size_t)blk * 32 + lane;
        float* yp = g_ys + blk * 32 + lane;            // + t*2048
        float (*sh)[32] = sm.k2.sh[wid];

        sh[0][lane] = h;
        __syncwarp();

        float4 buf[PF];

#define K2_STEP(T2, K)                                                        \
    {                                                                         \
        const float4 xg  = buf[K];                                            \
        const float4 hlo = *(const float4*)&sh[(K) & 1][bsub * 8];            \
        const float4 hhi = *(const float4*)&sh[(K) & 1][bsub * 8 + 4];        \
        float i0 = xg.x, f0 = xg.y, gg0 = xg.z, o0 = xg.w;                    \
        float i1 = 0.f, f1 = 0.f, gg1 = 0.f, o1 = 0.f;                        \
        f0  = fmaf(w[1][0], hlo.x, f0);  f1  = fmaf(w[1][4], hhi.x, f1);      \
        gg0 = fmaf(w[2][0], hlo.x, gg0); gg1 = fmaf(w[2][4], hhi.x, gg1);     \
        i0  = fmaf(w[0][0], hlo.x, i0);  i1  = fmaf(w[0][4], hhi.x, i1);      \
        o0  = fmaf(w[3][0], hlo.x, o0);  o1  = fmaf(w[3][4], hhi.x, o1);      \
        f0  = fmaf(w[1][1], hlo.y, f0);  f1  = fmaf(w[1][5], hhi.y, f1);      \
        gg0 = fmaf(w[2][1], hlo.y, gg0); gg1 = fmaf(w[2][5], hhi.y, gg1);     \
        i0  = fmaf(w[0][1], hlo.y, i0);  i1  = fmaf(w[0][5], hhi.y, i1);      \
        o0  = fmaf(w[3][1], hlo.y, o0);  o1  = fmaf(w[3][5], hhi.y, o1);      \
        f0  = fmaf(w[1][2], hlo.z, f0);  f1  = fmaf(w[1][6], hhi.z, f1);      \
        gg0 = fmaf(w[2][2], hlo.z, gg0); gg1 = fmaf(w[2][6], hhi.z, gg1);     \
        i0  = fmaf(w[0][2], hlo.z, i0);  i1  = fmaf(w[0][6], hhi.z, i1);      \
        o0  = fmaf(w[3][2], hlo.z, o0);  o1  = fmaf(w[3][6], hhi.z, o1);      \
        f0  = fmaf(w[1][3], hlo.w, f0);  f1  = fmaf(w[1][7], hhi.w, f1);      \
        gg0 = fmaf(w[2][3], hlo.w, gg0); gg1 = fmaf(w[2][7], hhi.w, gg1);     \
        i0  = fmaf(w[0][3], hlo.w, i0);  i1  = fmaf(w[0][7], hhi.w, i1);      \
        o0  = fmaf(w[3][3], hlo.w, o0);  o1  = fmaf(w[3][7], hhi.w, o1);      \
        const float vf = tanha(f0 + f1);                                      \
        const float vg = tanha(gg0 + gg1);                                    \
        const float vi = tanha(i0 + i1);                                      \
        const float vo = tanha(o0 + o1);                                      \
        const float fg = fmaf(vf, 0.5f, 0.5f);                                \
        const float ig = fmaf(vi, 0.5f, 0.5f);                                \
        const float og = fmaf(vo, 0.5f, 0.5f);                                \
        c = fmaf(fg, c, ig * vg);                                             \
        h = og * tanha(c);                                                    \
        sh[((K) & 1) ^ 1][lane] = h;                                          \
        yp[(size_t)(T2) * 2048] = h;                                          \
        int pfT = (T2) + PF; if (pfT > S_LEN - 1) pfT = S_LEN - 1;            \
        buf[K] = ldcg4(xp + (size_t)pfT * 2048);                              \
        __syncwarp();                                                         \
    }

        for (int ch = 0; ch < NCHUNK; ch++) {
            if (lane == 0) {
                while (atomicAdd(&g_k1done[ch], 0) < CHUNK_T) __nanosleep(256);
                if (ch + 1 < NCHUNK)
                    while (atomicAdd(&g_k1done[ch + 1], 0) < CHUNK_T) __nanosleep(256);
            }
            __syncwarp();
            __threadfence();

            if (ch == 0) {
#pragma unroll
                for (int k = 0; k < PF; k++)
                    buf[k] = ldcg4(xp + (size_t)k * 2048);
            }

            const int tbase = ch * CHUNK_T;
#pragma unroll 1
            for (int j = 0; j < CHUNK_T / PF; j++) {
                const int t0 = tbase + j * PF;
                K2_STEP(t0 + 0, 0) K2_STEP(t0 + 1, 1)
                K2_STEP(t0 + 2, 2) K2_STEP(t0 + 3, 3)
                K2_STEP(t0 + 4, 4) K2_STEP(t0 + 5, 5)
                K2_STEP(t0 + 6, 6) K2_STEP(t0 + 7, 7)
            }

            if (lane == 0) { __threadfence(); atomicAdd(&g_k2done[ch], 1); }
        }

        const size_t fb = (size_t)NROWS * OUTSZ;
        out[fb + blk * 32 + lane] = h;                          // h_f
        out[fb + BATCH * HID + blk * 32 + lane] = c;            // c_f
        return;
    }

    // =====================================================================
    // K3 role: bids [K2_CTAS+S_LEN, end). One CTA = one timestep t.
    // Gated on k2done[t/128] == 64 warps.
    // =====================================================================
    {
        const int t = bid - (K2_CTAS + S_LEN);

        for (int i = tid; i < NBLK; i += 256) {
            sm.k3.w1[i] = ((const float4*)rb_w1)[i];
            sm.k3.w2[i] = ((const float4*)rb_w2)[i];
            sm.k3.b2[i] = ((const float4*)rb_b2)[i];
            sm.k3.b1[i] = rb_b1[i];
        }

        if (tid == 0) {
            while (atomicAdd(&g_k2done[t >> 7], 0) < 64) __nanosleep(512);
            __threadfence();
        }
        __syncthreads();

        const int base = t * 256 + wid * 32;     // 8 warps x 32 rows = 256 rows
        const int e    = base + lane;

        const float4* hp = (const float4*)g_ys + (size_t)e * 2;
        const float4 ha = ldcg4(hp);
        const float4 hb = ldcg4(hp + 1);
        const float hv[8] = {ha.x, ha.y, ha.z, ha.w, hb.x, hb.y, hb.z, hb.w};

        float y[4];
#pragma unroll
        for (int i = 0; i < 4; i++) {
            float a = b_in[i];
#pragma unroll
            for (int j = 0; j < 8; j++) a = fmaf(w_in[i * 8 + j], hv[j], a);
            y[i] = leaky(a);
        }

#pragma unroll 2
        for (int blk = 0; blk < NBLK; blk++) {
            const float4 w1 = sm.k3.w1[blk];
            const float4 w2 = sm.k3.w2[blk];
            const float4 b2 = sm.k3.b2[blk];
            float z = sm.k3.b1[blk];
            z = fmaf(w1.x, y[0], z);
            z = fmaf(w1.y, y[1], z);
            z = fmaf(w1.z, y[2], z);
            z = fmaf(w1.w, y[3], z);
            z = leaky(z);
            y[0] = leaky(fmaf(w2.x, z, y[0]) + b2.x);
            y[1] = leaky(fmaf(w2.y, z, y[1]) + b2.y);
            y[2] = leaky(fmaf(w2.z, z, y[2]) + b2.z);
            y[3] = leaky(fmaf(w2.w, z, y[3]) + b2.w);
        }

        float yb = b_bn[0];
        yb = fmaf(w_bn[0], y[0], yb);
        yb = fmaf(w_bn[1], y[1], yb);
        yb = fmaf(w_bn[2], y[2], yb);
        yb = fmaf(w_bn[3], y[3], yb);
        yb = leaky(yb);

        // sigmoid(a*w+b) = 0.5 + 0.5*tanh(0.5*(a*w+b)) -> pre-halved w,b
        float4 wo = *(const float4*)(w_out + lane * 4);
        float4 bo = *(const float4*)(b_out + lane * 4);
        wo.x *= 0.5f; wo.y *= 0.5f; wo.z *= 0.5f; wo.w *= 0.5f;
        bo.x *= 0.5f; bo.y *= 0.5f; bo.z *= 0.5f; bo.w *= 0.5f;
        float* op = out + (size_t)base * OUTSZ + lane * 4;

#pragma unroll
        for (int cidx = 0; cidx < 32; cidx++) {
            const float ybc = __shfl_sync(0xffffffffu, yb, cidx);
            float4 o;
            o.x = fmaf(tanha(fmaf(ybc, wo.x, bo.x)), 0.5f, 0.5f);
            o.y = fmaf(tanha(fmaf(ybc, wo.y, bo.y)), 0.5f, 0.5f);
            o.z = fmaf(tanha(fmaf(ybc, wo.z, bo.z)), 0.5f, 0.5f);
            o.w = fmaf(tanha(fmaf(ybc, wo.w, bo.w)), 0.5f, 0.5f);
            *(float4*)(op + (size_t)cidx * OUTSZ) = o;
        }
    }
}

// ---------------------------------------------------------------------------
extern "C" void kernel_launch(void* const* d_in, const int* in_sizes, int n_in,
                              void* d_out, int out_size)
{
    const float* x     = (const float*)d_in[0];
    const float* h     = (const float*)d_in[1];
    const float* c     = (const float*)d_in[2];
    const float* w_ih  = (const float*)d_in[3];
    const float* w_hh  = (const float*)d_in[4];
    const float* b_ih  = (const float*)d_in[5];
    const float* b_hh  = (const float*)d_in[6];
    const float* w_in  = (const float*)d_in[7];
    const float* b_in  = (const float*)d_in[8];
    const float* rb_w1 = (const float*)d_in[9];
    const float* rb_b1 = (const float*)d_in[10];
    const float* rb_w2 = (const float*)d_in[11];
    const float* rb_b2 = (const float*)d_in[12];
    const float* w_bn  = (const float*)d_in[13];
    const float* b_bn  = (const float*)d_in[14];
    const float* w_out = (const float*)d_in[15];
    const float* b_out = (const float*)d_in[16];
    float* out = (float*)d_out;

    k0_reset<<<1, 32>>>();
    k_fused<<<K2_CTAS + S_LEN + S_LEN, 256>>>(
        x, h, c, w_ih, w_hh, b_ih, b_hh,
        w_in, b_in, rb_w1, rb_b1, rb_w2, rb_b2,
        w_bn, b_bn, w_out, b_out, out);
}

// round 10
// speedup vs baseline: 5.7829x; 5.7829x over previous
#include <cuda_runtime.h>
#include <cstdint>

#define S_LEN 2048
#define BATCH 256
#define HID   8
#define NBLK  80
#define OUTSZ 128
#define NROWS (S_LEN*BATCH)   // 524288
#define CHUNK_T 128
#define NCHUNK  (S_LEN/CHUNK_T)   // 16
#define K2_CTAS 64
#define K3_CTAS 84
#define PF 8

// Scratch (__device__ globals; no runtime allocation)
// g_xg layout: [row][unit*4 + gate_type], row = t*BATCH + b
__device__ float g_xg[(size_t)NROWS * 32];   // 64 MB
__device__ float g_ys[(size_t)NROWS * HID];  // 16 MB
__device__ int   g_k2done[NCHUNK];

__device__ __forceinline__ float tanha(float x) {
    float r; asm("tanh.approx.f32 %0, %1;" : "=f"(r) : "f"(x)); return r;
}
__device__ __forceinline__ float leaky(float v) { return fmaxf(v, 0.01f * v); }
__device__ __forceinline__ float4 ldcg4(const float4* p) {
    float4 v;
    asm volatile("ld.global.cg.v4.f32 {%0,%1,%2,%3},[%4];"
                 : "=f"(v.x), "=f"(v.y), "=f"(v.z), "=f"(v.w) : "l"(p));
    return v;
}
__device__ __forceinline__ unsigned long long pack2(float a, float b) {
    unsigned long long r;
    asm("mov.b64 %0, {%1, %2};" : "=l"(r) : "f"(a), "f"(b));
    return r;
}
__device__ __forceinline__ unsigned long long pk0(float a) {
    return pack2(a, 0.0f);
}
__device__ __forceinline__ unsigned long long fma2(
    unsigned long long a, unsigned long long b, unsigned long long c) {
    unsigned long long d;
    asm("fma.rn.f32x2 %0, %1, %2, %3;" : "=l"(d) : "l"(a), "l"(b), "l"(c));
    return d;
}
__device__ __forceinline__ float hadd2(unsigned long long a) {
    float lo, hi;
    asm("mov.b64 {%0, %1}, %2;" : "=f"(lo), "=f"(hi) : "l"(a));
    return lo + hi;
}
__device__ __forceinline__ int ld_acq(const int* p) {
    int v;
    asm volatile("ld.acquire.gpu.global.u32 %0, [%1];" : "=r"(v) : "l"(p));
    return v;
}

// ---------------------------------------------------------------------------
// K1: xg[row][u*4+ty] = s(ty) * ( x[row].w_ih[ty*8+u] + b_ih + b_hh )
//     s = 0.5 for sigmoid gates (i,f,o), 1.0 for tanh gate.
//     Also resets the chunk flags for the following fused kernel.
// ---------------------------------------------------------------------------
__global__ void __launch_bounds__(256) k1_xw(
    const float* __restrict__ x, const float* __restrict__ w_ih,
    const float* __restrict__ b_ih, const float* __restrict__ b_hh)
{
    __shared__ float4 sx[256 * 8];     // 32 KB: 256 rows of x
    __shared__ float  swp[32 * 33];    // padded weights

    const int tid  = threadIdx.x;
    const int lane = tid & 31;
    const int wid  = tid >> 5;

    if (blockIdx.x == 0 && tid < NCHUNK) g_k2done[tid] = 0;

#pragma unroll
    for (int k = 0; k < 4; k++) {
        const int idx = tid + k * 256;          // 1024 floats
        const int g = idx >> 5, j = idx & 31;
        const float s = ((g >> 3) == 2) ? 1.f : 0.5f;
        swp[g * 33 + j] = w_ih[idx] * s;
    }

    const size_t rowbase = (size_t)blockIdx.x * 256;
    const float4* xg4 = (const float4*)x + rowbase * 8;
#pragma unroll
    for (int i = 0; i < 8; i++) sx[tid + i * 256] = xg4[tid + i * 256];

    __syncthreads();

    float w[32];
#pragma unroll
    for (int j = 0; j < 32; j++) w[j] = swp[lane * 33 + j];
    const float s2 = ((lane >> 3) == 2) ? 1.f : 0.5f;
    const float bias = (b_ih[lane] + b_hh[lane]) * s2;

    const int ocol = (lane & 7) * 4 + (lane >> 3);   // unit-major column
    float* op = g_xg + (rowbase + wid * 32) * 32 + ocol;
    const float4* xr0 = &sx[wid * 32 * 8];

#pragma unroll 4
    for (int r = 0; r < 32; r++) {
        const float4* xr = xr0 + r * 8;
        float a0 = bias, a1 = 0.f, a2 = 0.f, a3 = 0.f;
#pragma unroll
        for (int j4 = 0; j4 < 8; j4++) {
            const float4 v = xr[j4];            // broadcast LDS.128
            a0 = fmaf(w[j4 * 4 + 0], v.x, a0);
            a1 = fmaf(w[j4 * 4 + 1], v.y, a1);
            a2 = fmaf(w[j4 * 4 + 2], v.z, a2);
            a3 = fmaf(w[j4 * 4 + 3], v.w, a3);
        }
        op[(size_t)r * 32] = (a0 + a1) + (a2 + a3);   // coalesced STG.32
    }
}

// ---------------------------------------------------------------------------
// K23: fused LSTM (producer, bids 0..63, one warp each on its own SM) +
//      residual head (consumer, bids 64..147, persistent, chunk-gated).
// ---------------------------------------------------------------------------
__global__ void __launch_bounds__(256) k23(
    const float* __restrict__ h0,    const float* __restrict__ c0,
    const float* __restrict__ w_hh,
    const float* __restrict__ w_in,  const float* __restrict__ b_in,
    const float* __restrict__ rb_w1, const float* __restrict__ rb_b1,
    const float* __restrict__ rb_w2, const float* __restrict__ rb_b2,
    const float* __restrict__ w_bn,  const float* __restrict__ b_bn,
    const float* __restrict__ w_out, const float* __restrict__ b_out,
    float* __restrict__ out)
{
    __shared__ __align__(16) float sh[2][32];            // k2 h exchange
    __shared__ float4 s_w1[NBLK], s_w2[NBLK], s_b2[NBLK];
    __shared__ float  s_b1[NBLK];

    const int bid  = blockIdx.x;
    const int tid  = threadIdx.x;
    const int lane = tid & 31;
    const int wid  = tid >> 5;

    // =====================================================================
    // K2 role: sequential LSTM, 4 chains/warp, f32x2-packed gate dots.
    // =====================================================================
    if (bid < K2_CTAS) {
        if (wid != 0) return;                   // one warp per CTA
        const int blk  = bid;                   // 0..63
        const int unit = lane & 7;
        const int bsub = lane >> 3;

        // packed weights: wp[gate][jpair] = (w[2p], w[2p+1]) pre-scaled
        unsigned long long wp[4][4];
#pragma unroll
        for (int ty = 0; ty < 4; ty++) {
            const float s = (ty == 2) ? 1.f : 0.5f;
            const float* wr = w_hh + (ty * 8 + unit) * 8;
#pragma unroll
            for (int p = 0; p < 4; p++)
                wp[ty][p] = pack2(wr[2 * p] * s, wr[2 * p + 1] * s);
        }

        float h = h0[blk * 32 + lane];
        float c = c0[blk * 32 + lane];

        const float4* xp = (const float4*)g_xg + (size_t)blk * 32 + lane;
        float* yp = g_ys + blk * 32 + lane;            // + t*2048

        sh[0][lane] = h;
        __syncwarp();

        float4 buf[PF];
#pragma unroll
        for (int k = 0; k < PF; k++) buf[k] = __ldg(xp + (size_t)k * 2048);

#define K2_STEP(T2, K)                                                        \
    {                                                                         \
        const float4 xg = buf[K];                                             \
        const ulonglong2 h01 = *(const ulonglong2*)&sh[(K) & 1][bsub * 8];    \
        const ulonglong2 h23 = *(const ulonglong2*)&sh[(K) & 1][bsub * 8 + 4];\
        unsigned long long ai = pk0(xg.x), af = pk0(xg.y);                    \
        unsigned long long ag = pk0(xg.z), ao = pk0(xg.w);                    \
        af = fma2(wp[1][0], h01.x, af); ag = fma2(wp[2][0], h01.x, ag);       \
        ai = fma2(wp[0][0], h01.x, ai); ao = fma2(wp[3][0], h01.x, ao);       \
        af = fma2(wp[1][1], h01.y, af); ag = fma2(wp[2][1], h01.y, ag);       \
        ai = fma2(wp[0][1], h01.y, ai); ao = fma2(wp[3][1], h01.y, ao);       \
        af = fma2(wp[1][2], h23.x, af); ag = fma2(wp[2][2], h23.x, ag);       \
        ai = fma2(wp[0][2], h23.x, ai); ao = fma2(wp[3][2], h23.x, ao);       \
        af = fma2(wp[1][3], h23.y, af); ag = fma2(wp[2][3], h23.y, ag);       \
        ai = fma2(wp[0][3], h23.y, ai); ao = fma2(wp[3][3], h23.y, ao);       \
        const float vf = tanha(hadd2(af));                                    \
        const float vg = tanha(hadd2(ag));                                    \
        const float vi = tanha(hadd2(ai));                                    \
        const float vo = tanha(hadd2(ao));                                    \
        const float fg = fmaf(vf, 0.5f, 0.5f);                                \
        const float ig = fmaf(vi, 0.5f, 0.5f);                                \
        const float og = fmaf(vo, 0.5f, 0.5f);                                \
        c = fmaf(fg, c, ig * vg);                                             \
        h = og * tanha(c);                                                    \
        sh[((K) & 1) ^ 1][lane] = h;                                          \
        yp[(size_t)(T2) * 2048] = h;                                          \
        int pfT = (T2) + PF; if (pfT >= S_LEN) pfT = S_LEN - 1;               \
        buf[K] = __ldg(xp + (size_t)pfT * 2048);                              \
        __syncwarp();                                                         \
    }

        for (int ch = 0; ch < NCHUNK; ch++) {
            const int tbase = ch * CHUNK_T;
#pragma unroll 1
            for (int j = 0; j < CHUNK_T / PF; j++) {
                const int t0 = tbase + j * PF;
                K2_STEP(t0 + 0, 0) K2_STEP(t0 + 1, 1)
                K2_STEP(t0 + 2, 2) K2_STEP(t0 + 3, 3)
                K2_STEP(t0 + 4, 4) K2_STEP(t0 + 5, 5)
                K2_STEP(t0 + 6, 6) K2_STEP(t0 + 7, 7)
            }
            if (lane == 0) { __threadfence(); atomicAdd(&g_k2done[ch], 1); }
        }

        const size_t fb = (size_t)NROWS * OUTSZ;
        out[fb + blk * 32 + lane] = h;                          // h_f
        out[fb + BATCH * HID + blk * 32 + lane] = c;            // c_f
        return;
    }

    // =====================================================================
    // K3 role: persistent consumer CTAs. Per chunk: wait for all 64 k2
    // warps, then process this CTA's share of the chunk's 1024 row-blocks.
    // =====================================================================
    {
        const int cta = bid - K2_CTAS;         // 0..83

        for (int i = tid; i < NBLK; i += 256) {
            s_w1[i] = ((const float4*)rb_w1)[i];
            s_w2[i] = ((const float4*)rb_w2)[i];
            s_b2[i] = ((const float4*)rb_b2)[i];
            s_b1[i] = rb_b1[i];
        }
        __syncthreads();

        // per-thread constants
        float win[4][8], bin[4];
#pragma unroll
        for (int i = 0; i < 4; i++) {
            bin[i] = b_in[i];
#pragma unroll
            for (int j = 0; j < 8; j++) win[i][j] = w_in[i * 8 + j];
        }
        const float wbn0 = w_bn[0], wbn1 = w_bn[1], wbn2 = w_bn[2], wbn3 = w_bn[3];
        const float bbn = b_bn[0];
        // sigmoid(a*w+b) = 0.5 + 0.5*tanh(0.5*(a*w+b)) -> pre-halved w,b
        float4 wo = *(const float4*)(w_out + lane * 4);
        float4 bo = *(const float4*)(b_out + lane * 4);
        wo.x *= 0.5f; wo.y *= 0.5f; wo.z *= 0.5f; wo.w *= 0.5f;
        bo.x *= 0.5f; bo.y *= 0.5f; bo.z *= 0.5f; bo.w *= 0.5f;

        for (int ch = 0; ch < NCHUNK; ch++) {
            if (tid == 0) {
                while (ld_acq(&g_k2done[ch]) < K2_CTAS) __nanosleep(1024);
            }
            __syncthreads();

            // chunk rows: [ch*32768, (ch+1)*32768), 1024 blocks of 32
            for (int rb = cta * 8 + wid; rb < 1024; rb += K3_CTAS * 8) {
                const int base = ch * (CHUNK_T * BATCH) + rb * 32;
                const int e    = base + lane;

                const float4* hp = (const float4*)g_ys + (size_t)e * 2;
                const float4 ha = ldcg4(hp);
                const float4 hb = ldcg4(hp + 1);
                const float hv[8] = {ha.x, ha.y, ha.z, ha.w,
                                     hb.x, hb.y, hb.z, hb.w};

                float y[4];
#pragma unroll
                for (int i = 0; i < 4; i++) {
                    float a = bin[i];
#pragma unroll
                    for (int j = 0; j < 8; j++) a = fmaf(win[i][j], hv[j], a);
                    y[i] = leaky(a);
                }

#pragma unroll 2
                for (int blk = 0; blk < NBLK; blk++) {
                    const float4 w1 = s_w1[blk];
                    const float4 w2 = s_w2[blk];
                    const float4 b2 = s_b2[blk];
                    float z = s_b1[blk];
                    z = fmaf(w1.x, y[0], z);
                    z = fmaf(w1.y, y[1], z);
                    z = fmaf(w1.z, y[2], z);
                    z = fmaf(w1.w, y[3], z);
                    z = leaky(z);
                    y[0] = leaky(fmaf(w2.x, z, y[0]) + b2.x);
                    y[1] = leaky(fmaf(w2.y, z, y[1]) + b2.y);
                    y[2] = leaky(fmaf(w2.z, z, y[2]) + b2.z);
                    y[3] = leaky(fmaf(w2.w, z, y[3]) + b2.w);
                }

                float yb = bbn;
                yb = fmaf(wbn0, y[0], yb);
                yb = fmaf(wbn1, y[1], yb);
                yb = fmaf(wbn2, y[2], yb);
                yb = fmaf(wbn3, y[3], yb);
                yb = leaky(yb);

                float* op = out + (size_t)base * OUTSZ + lane * 4;
#pragma unroll
                for (int cidx = 0; cidx < 32; cidx++) {
                    const float ybc = __shfl_sync(0xffffffffu, yb, cidx);
                    float4 o;
                    o.x = fmaf(tanha(fmaf(ybc, wo.x, bo.x)), 0.5f, 0.5f);
                    o.y = fmaf(tanha(fmaf(ybc, wo.y, bo.y)), 0.5f, 0.5f);
                    o.z = fmaf(tanha(fmaf(ybc, wo.z, bo.z)), 0.5f, 0.5f);
                    o.w = fmaf(tanha(fmaf(ybc, wo.w, bo.w)), 0.5f, 0.5f);
                    *(float4*)(op + (size_t)cidx * OUTSZ) = o;
                }
            }
        }
    }
}

// ---------------------------------------------------------------------------
extern "C" void kernel_launch(void* const* d_in, const int* in_sizes, int n_in,
                              void* d_out, int out_size)
{
    const float* x     = (const float*)d_in[0];
    const float* h     = (const float*)d_in[1];
    const float* c     = (const float*)d_in[2];
    const float* w_ih  = (const float*)d_in[3];
    const float* w_hh  = (const float*)d_in[4];
    const float* b_ih  = (const float*)d_in[5];
    const float* b_hh  = (const float*)d_in[6];
    const float* w_in  = (const float*)d_in[7];
    const float* b_in  = (const float*)d_in[8];
    const float* rb_w1 = (const float*)d_in[9];
    const float* rb_b1 = (const float*)d_in[10];
    const float* rb_w2 = (const float*)d_in[11];
    const float* rb_b2 = (const float*)d_in[12];
    const float* w_bn  = (const float*)d_in[13];
    const float* b_bn  = (const float*)d_in[14];
    const float* w_out = (const float*)d_in[15];
    const float* b_out = (const float*)d_in[16];
    float* out = (float*)d_out;

    k1_xw<<<2048, 256>>>(x, w_ih, b_ih, b_hh);
    k23<<<K2_CTAS + K3_CTAS, 256>>>(h, c, w_hh,
                                    w_in, b_in, rb_w1, rb_b1, rb_w2, rb_b2,
                                    w_bn, b_bn, w_out, b_out, out);
}